// round 17
// baseline (speedup 1.0000x reference)
#include <cuda_runtime.h>
#include <cuda_bf16.h>
#include <cstdint>

#define B 8
#define C 2048
#define D 128
#define J 128
#define CM2 (C - 2)   // 2046
#define BCD (B * C * D)

// ---------------- scratch (device globals) ----------------
__device__ __align__(16) __nv_bfloat16 g_vT[B * D * C];
__device__ __align__(16) float g_mx[3 * BCD];
__device__ __align__(16) float g_beW[B * 2 * D];
__device__ float g_colsum[B * D];
__device__ float g_sq[B * C];
__device__ float g_sk[B * C];
__device__ float g_uq[D];
__device__ float g_uk[D];
__device__ float g_c[2];
__device__ float g_bc0[D];
__device__ float g_bc3[D];
__device__ __align__(16) __nv_bfloat16 g_Wbh[512 * D];
__device__ __align__(16) __nv_bfloat16 g_Wbl[512 * D];
__device__ __align__(16) __nv_bfloat16 g_Wch[D * D];

// ---------------- helpers ----------------
__device__ __forceinline__ uint32_t smem_u32(const void* p) {
    uint32_t a;
    asm("{ .reg .u64 tmp; cvta.to.shared.u64 tmp, %1; cvt.u32.u64 %0, tmp; }"
        : "=r"(a) : "l"(p));
    return a;
}
#define CVT_BF16X2(res, a, b) \
    asm("cvt.rn.satfinite.bf16x2.f32 %0, %1, %2;" : "=r"(res) : "f"(b), "f"(a))
#define SWZ(x) ((x) ^ (((x) >> 3) & 0x70))

__device__ __forceinline__ void ldm_x4(uint32_t& r0, uint32_t& r1, uint32_t& r2,
                                       uint32_t& r3, uint32_t addr) {
    asm volatile("ldmatrix.sync.aligned.m8n8.x4.shared.b16 {%0,%1,%2,%3}, [%4];"
                 : "=r"(r0), "=r"(r1), "=r"(r2), "=r"(r3) : "r"(addr));
}
__device__ __forceinline__ void mma16816(float* c, uint32_t a0, uint32_t a1,
                                         uint32_t a2, uint32_t a3,
                                         uint32_t b0, uint32_t b1) {
    asm volatile(
        "mma.sync.aligned.m16n8k16.row.col.f32.bf16.bf16.f32 "
        "{%0,%1,%2,%3}, {%4,%5,%6,%7}, {%8,%9}, {%0,%1,%2,%3};"
        : "+f"(c[0]), "+f"(c[1]), "+f"(c[2]), "+f"(c[3])
        : "r"(a0), "r"(a1), "r"(a2), "r"(a3), "r"(b0), "r"(b1));
}
__device__ __forceinline__ void split2(float x0, float x1, uint32_t& hp, uint32_t& lp) {
    CVT_BF16X2(hp, x0, x1);
    __nv_bfloat162 hv = *reinterpret_cast<__nv_bfloat162*>(&hp);
    float f0 = __bfloat162float(hv.x), f1 = __bfloat162float(hv.y);
    CVT_BF16X2(lp, x0 - f0, x1 - f1);
}
__device__ __forceinline__ void mma_pass64(uint32_t suA, uint32_t suB, float cc[8][4],
                                           int rowA, int colAg, int nh,
                                           int rowBoff, int colBg) {
    #pragma unroll
    for (int ks = 0; ks < 4; ks++) {
        uint32_t a0, a1, a2, a3;
        ldm_x4(a0, a1, a2, a3, suA + SWZ(rowA * 128 + ks * 32 + colAg));
        #pragma unroll
        for (int nt = 0; nt < 8; nt += 2) {
            uint32_t b0, b1, b2, b3;
            int rowB = (nh << 6) + nt * 8 + rowBoff;
            ldm_x4(b0, b1, b2, b3, suB + SWZ(rowB * 128 + ks * 32 + colBg));
            mma16816(cc[nt],     a0, a1, a2, a3, b0, b1);
            mma16816(cc[nt + 1], a0, a1, a2, a3, b2, b3);
        }
    }
}

#define SMEM_MMA2 (49152 + 1024)
#define SMEM_ATTN (49152 + 1024)

// ---------------- K0: folded + split/transposed weights ----------------
// grid 161, block 128
__global__ void k_pre(const float* __restrict__ W_qkv, const float* __restrict__ b_qkv,
                      const float* __restrict__ w_score, const float* __restrict__ b_score,
                      const float* __restrict__ W_out, const float* __restrict__ b_out,
                      const float* __restrict__ W_mix2, const float* __restrict__ b_mix2,
                      const float* __restrict__ W_mix3, const float* __restrict__ b_mix3) {
    int t = threadIdx.x;
    int blk = blockIdx.x;
    __shared__ __align__(16) float srow[4][D];

    if (blk < 32 || (blk >= 33 && blk < 129)) {
        bool isWc = (blk < 32);
        int kr0 = isWc ? blk * 4 : (blk - 33) * 4;
        const float* Wsrc = isWc ? W_out : W_mix3;
        const float* W2base = isWc ? (W_mix2 + (size_t)D * D) : W_mix2;
        #pragma unroll
        for (int j = 0; j < 4; j++)
            srow[j][t] = Wsrc[(size_t)(kr0 + j) * D + t];
        __syncthreads();
        float a0 = 0.f, a1 = 0.f, a2 = 0.f, a3 = 0.f;
        #pragma unroll
        for (int m0 = 0; m0 < 128; m0 += 16) {
            float wbuf[16];
            #pragma unroll
            for (int j = 0; j < 16; j++)
                wbuf[j] = W2base[(size_t)(m0 + j) * D + t];
            #pragma unroll
            for (int j = 0; j < 16; j++) {
                float w2 = wbuf[j];
                a0 += srow[0][m0 + j] * w2;
                a1 += srow[1][m0 + j] * w2;
                a2 += srow[2][m0 + j] * w2;
                a3 += srow[3][m0 + j] * w2;
            }
        }
        float accs[4] = {a0, a1, a2, a3};
        if (isWc) {
            #pragma unroll
            for (int j = 0; j < 4; j++)
                g_Wch[t * 128 + kr0 + j] = __float2bfloat16(accs[j]);
        } else {
            #pragma unroll
            for (int j = 0; j < 4; j++) {
                int kr = kr0 + j;
                int x = kr >> 7, k = kr & 127;
                __nv_bfloat16 h = __float2bfloat16(accs[j]);
                g_Wbh[(x * 128 + t) * 128 + k] = h;
                g_Wbl[(x * 128 + t) * 128 + k] =
                    __float2bfloat16(accs[j] - __bfloat162float(h));
            }
        }
    } else if (blk == 32) {
        __shared__ float sbm[D], sbo[D];
        sbm[t] = b_mix3[t];
        sbo[t] = b_out[t];
        __syncthreads();
        float bc0 = b_mix2[t];
        float bc3 = 0.f;
        #pragma unroll
        for (int m0 = 0; m0 < 128; m0 += 8) {
            float wa[8], wb[8];
            #pragma unroll
            for (int j = 0; j < 8; j++) {
                wa[j] = W_mix2[(size_t)(m0 + j) * D + t];
                wb[j] = W_mix2[(size_t)(D + m0 + j) * D + t];
            }
            #pragma unroll
            for (int j = 0; j < 8; j++) {
                bc3 += sbm[m0 + j] * wa[j];
                bc0 += sbo[m0 + j] * wb[j];
            }
        }
        g_bc0[t] = bc0;
        g_bc3[t] = bc3 + bc0;
        #pragma unroll
        for (int i = t; i < B * D; i += 128) g_colsum[i] = 0.f;
        __shared__ float s1[D], s2[D];
        s1[t] = b_qkv[t] * w_score[t];
        s2[t] = b_qkv[D + t] * w_score[D + t];
        __syncthreads();
        for (int off = 64; off; off >>= 1) {
            if (t < off) { s1[t] += s1[t + off]; s2[t] += s2[t + off]; }
            __syncthreads();
        }
        if (t == 0) { g_c[0] = s1[0]; g_c[1] = s2[0] + b_score[0]; }
    } else if (blk < 145) {
        int k0 = (blk - 129) * 8;
        float wv[8];
        #pragma unroll
        for (int j = 0; j < 8; j++)
            wv[j] = W_qkv[(k0 + j) * 3 * D + 2 * D + t];
        #pragma unroll
        for (int j = 0; j < 8; j++) {
            int k = k0 + j;
            __nv_bfloat16 h = __float2bfloat16(wv[j]);
            g_Wbh[(384 + t) * 128 + k] = h;
            g_Wbl[(384 + t) * 128 + k] = __float2bfloat16(wv[j] - __bfloat162float(h));
        }
    } else {
        __shared__ float sws[2 * D];
        sws[t] = w_score[t];
        sws[D + t] = w_score[D + t];
        __syncthreads();
        int row = (blk - 145) * 8 + (t >> 4);
        int seg = t & 15;
        const float* qr = W_qkv + (size_t)row * 3 * D;
        float4 qa = *(const float4*)(qr + seg * 8);
        float4 qb = *(const float4*)(qr + seg * 8 + 4);
        float4 ka = *(const float4*)(qr + D + seg * 8);
        float4 kb = *(const float4*)(qr + D + seg * 8 + 4);
        float4 w0 = *(const float4*)&sws[seg * 8];
        float4 w1 = *(const float4*)&sws[seg * 8 + 4];
        float4 w2 = *(const float4*)&sws[D + seg * 8];
        float4 w3 = *(const float4*)&sws[D + seg * 8 + 4];
        float uq = qa.x * w0.x + qa.y * w0.y + qa.z * w0.z + qa.w * w0.w
                 + qb.x * w1.x + qb.y * w1.y + qb.z * w1.z + qb.w * w1.w;
        float uk = ka.x * w2.x + ka.y * w2.y + ka.z * w2.z + ka.w * w2.w
                 + kb.x * w3.x + kb.y * w3.y + kb.z * w3.z + kb.w * w3.w;
        #pragma unroll
        for (int off = 8; off; off >>= 1) {
            uq += __shfl_down_sync(0xffffffffu, uq, off);
            uk += __shfl_down_sync(0xffffffffu, uk, off);
        }
        if (seg == 0) { g_uq[row] = uq; g_uk[row] = uk; }
    }
}

// ---------------- K1: big GEMM ops @ [W3a'|W3b'|W3c'|Wv] + begin/end side blocks ----------------
// grid 1024+16, block 256, dyn smem 48KB, occ 2
__global__ void __launch_bounds__(256, 2) k_gemm(
    const float* __restrict__ ops, const float* __restrict__ b_qkv,
    const int* __restrict__ bidx, const int* __restrict__ eidx,
    const float* __restrict__ W_begin, const float* __restrict__ b_begin,
    const float* __restrict__ W_end, const float* __restrict__ b_end,
    const float* __restrict__ W_mix2) {
    __shared__ float sbv[128];
    __shared__ float suq[128], suk[128];
    extern __shared__ __align__(16) char dsm[];
    char* smb = (char*)((((uintptr_t)dsm) + 1023) & ~(uintptr_t)1023);
    char* smAh = smb;
    char* smAl = smb + 8192;
    char* smBh = smb + 16384;
    char* smBl = smb + 32768;
    uint32_t suAh = smem_u32(smAh), suAl = smem_u32(smAl);
    uint32_t suBh = smem_u32(smBh), suBl = smem_u32(smBl);

    int blk = blockIdx.x;
    int t = threadIdx.x;

    if (blk >= 1024) {
        int e = blk - 1024;
        int b = e >> 1, which = e & 1;
        const int* idx = which ? eidx : bidx;
        if (t < 128) {
            float s = 0.f;
            for (int j = 0; j < J; j++)
                s += ops[((size_t)b * C + idx[b * J + j]) * D + t];
            suq[t] = s * (1.0f / (float)J);
        }
        __syncthreads();
        if (t < 128) {
            const float* W = which ? W_end : W_begin;
            const float* bbp = which ? b_end : b_begin;
            float acc = bbp[t];
            #pragma unroll 8
            for (int k = 0; k < D; k++) acc += suq[k] * W[k * D + t];
            suk[t] = acc;
        }
        __syncthreads();
        if (t < 128) {
            float acc2 = g_bc0[t];
            #pragma unroll 8
            for (int k = 0; k < D; k++) acc2 += suk[k] * W_mix2[k * D + t];
            g_beW[((size_t)b * 2 + which) * D + t] = acc2;
        }
        return;
    }

    int mt = blk >> 2, ng = blk & 3;
    int b = mt >> 5;
    int i0 = (mt & 31) * 64;
    int w = t >> 5, lane = t & 31;

    if (ng == 3 && t < 128) sbv[t] = b_qkv[2 * D + t];
    if (ng == 0 && t < 128) { suq[t] = g_uq[t]; suk[t] = g_uk[t]; }
    __syncthreads();

    float cc[8][4];
    #pragma unroll
    for (int nt = 0; nt < 8; nt++)
        #pragma unroll
        for (int r = 0; r < 4; r++) cc[nt][r] = 0.f;

    int l8 = lane & 7, grp = lane >> 3;
    int mg = w >> 1, nh = w & 1;
    int rowA = (mg << 4) + l8 + ((grp & 1) << 3);
    int colAg = (grp >> 1) << 4;
    int rowBoff = l8 + ((grp >> 1) << 3);
    int colBg = (grp & 1) << 4;

    int r = t >> 2, h = t & 3;
    int rowoff = r * 128 + h * 32;
    float dq = 0.f, dk = 0.f;

    #pragma unroll 1
    for (int c = 0; c < 2; c++) {
        if (c) __syncthreads();
        const float4* src = (const float4*)
            (ops + ((size_t)b * C + i0 + r) * D + c * 64 + h * 16);
        #pragma unroll
        for (int q = 0; q < 4; q++) {
            float4 v = src[q];
            if (ng == 0) {
                float4 u4 = *(const float4*)&suq[c * 64 + h * 16 + q * 4];
                float4 k4 = *(const float4*)&suk[c * 64 + h * 16 + q * 4];
                dq += v.x * u4.x + v.y * u4.y + v.z * u4.z + v.w * u4.w;
                dk += v.x * k4.x + v.y * k4.y + v.z * k4.z + v.w * k4.w;
            }
            uint32_t h0, h1, l0, l1;
            split2(v.x, v.y, h0, l0);
            split2(v.z, v.w, h1, l1);
            uint32_t off = rowoff + q * 8;
            *(uint2*)(smAh + SWZ(off)) = make_uint2(h0, h1);
            *(uint2*)(smAl + SWZ(off)) = make_uint2(l0, l1);
        }
        #pragma unroll
        for (int c2 = 0; c2 < 4; c2++) {
            int idx = t + c2 * 256;
            int dd = idx >> 3, ccx = idx & 7;
            uint32_t off = dd * 128 + ccx * 16;
            int gsrc = (ng * 128 + dd) * 128 + c * 64 + ccx * 8;
            *(uint4*)(smBh + SWZ(off)) = *(const uint4*)&g_Wbh[gsrc];
            if (ng < 3)
                *(uint4*)(smBl + SWZ(off)) = *(const uint4*)&g_Wbl[gsrc];
        }
        __syncthreads();
        mma_pass64(suAh, suBh, cc, rowA, colAg, nh, rowBoff, colBg);
        if (ng < 3) {
            mma_pass64(suAh, suBl, cc, rowA, colAg, nh, rowBoff, colBg);
            mma_pass64(suAl, suBh, cc, rowA, colAg, nh, rowBoff, colBg);
        }
    }

    if (ng == 0) {
        dq += __shfl_xor_sync(0xffffffffu, dq, 1);
        dk += __shfl_xor_sync(0xffffffffu, dk, 1);
        dq += __shfl_xor_sync(0xffffffffu, dq, 2);
        dk += __shfl_xor_sync(0xffffffffu, dk, 2);
        if (h == 0) {
            int row = b * C + i0 + r;
            g_sq[row] = dq + g_c[0];
            g_sk[row] = dk + g_c[1];
        }
    }

    int quad = lane >> 2, qt = lane & 3;
    if (ng < 3) {
        float* ob = g_mx + (size_t)ng * BCD + (size_t)b * C * D;
        int r0g = i0 + (mg << 4) + quad;
        #pragma unroll
        for (int nt = 0; nt < 8; nt++) {
            int n0 = (nh << 6) + nt * 8 + 2 * qt;
            *(float2*)&ob[(size_t)r0g * D + n0] = make_float2(cc[nt][0], cc[nt][1]);
            *(float2*)&ob[(size_t)(r0g + 8) * D + n0] = make_float2(cc[nt][2], cc[nt][3]);
        }
    } else {
        __syncthreads();
        __nv_bfloat16* vst = (__nv_bfloat16*)smb;
        int m0 = (mg << 4) + quad, m8 = m0 + 8;
        #pragma unroll
        for (int nt = 0; nt < 8; nt++) {
            int n0 = (nh << 6) + nt * 8 + 2 * qt;
            float vb0 = sbv[n0], vb1 = sbv[n0 + 1];
            vst[n0 * 64 + m0]       = __float2bfloat16(cc[nt][0] + vb0);
            vst[(n0 + 1) * 64 + m0] = __float2bfloat16(cc[nt][1] + vb1);
            vst[n0 * 64 + m8]       = __float2bfloat16(cc[nt][2] + vb0);
            vst[(n0 + 1) * 64 + m8] = __float2bfloat16(cc[nt][3] + vb1);
        }
        __syncthreads();
        int n = t >> 1, hh = t & 1;
        const uint4* srcv = (const uint4*)(vst + n * 64 + hh * 32);
        uint4* dstv = (uint4*)(g_vT + ((size_t)b * D + n) * C + i0 + hh * 32);
        #pragma unroll
        for (int q = 0; q < 4; q++) dstv[q] = srcv[q];
        if (t < 128) {
            float s = 0.f;
            #pragma unroll 16
            for (int m = 0; m < 64; m++) s += __bfloat162float(vst[t * 64 + m]);
            atomicAdd(&g_colsum[b * D + t], s);
        }
    }
}

// ---------------- K2: attention HMMA, double-buffered tiles ----------------
// grid 256, block 256, dyn smem 48KB, occ 2
__global__ void __launch_bounds__(256, 2) k_attn(const float* __restrict__ mask,
                                                 const int* __restrict__ rel,
                                                 float* __restrict__ out) {
    extern __shared__ __align__(16) char dsm[];
    char* smb = (char*)((((uintptr_t)dsm) + 1023) & ~(uintptr_t)1023);
    char* pA[2] = {smb, smb + 8192};
    char* pB[2] = {smb + 16384, smb + 32768};
    uint32_t sA[2] = {smem_u32(pA[0]), smem_u32(pA[1])};
    uint32_t sB[2] = {smem_u32(pB[0]), smem_u32(pB[1])};

    __shared__ float ssq[64];
    __shared__ float srow[64];
    __shared__ float scol[128];
    __shared__ float sb3[128];
    __shared__ int2 srel[64];

    int t = threadIdx.x;
    int blk = blockIdx.x;
    int w = t >> 5, lane = t & 31;
    int b = blk >> 5;
    int i0 = (blk & 31) * 64;
    int base = b * C;

    if (t < 64) {
        ssq[t] = g_sq[base + i0 + t];
        int ig = i0 + t;
        srel[t] = (ig < CM2) ? *(const int2*)&rel[((size_t)b * CM2 + ig) * 2]
                             : make_int2(0, 0);
    }
    if (t < 128) { scol[t] = g_colsum[b * D + t]; sb3[t] = g_bc3[t]; }

    float rowsum[8];
    #pragma unroll
    for (int s = 0; s < 8; s++) rowsum[s] = 0.f;

    float cc[8][4];
    #pragma unroll
    for (int nt = 0; nt < 8; nt++)
        #pragma unroll
        for (int r = 0; r < 4; r++) cc[nt][r] = 0.f;

    const __nv_bfloat16* vTb = g_vT + (size_t)b * D * C;

    int l8 = lane & 7, grp = lane >> 3;
    int mg = w >> 1, nh = w & 1;
    int rowA = (mg << 4) + l8 + ((grp & 1) << 3);
    int colAg = (grp >> 1) << 4;
    int rowBoff = l8 + ((grp >> 1) << 3);
    int colBg = (grp & 1) << 4;

    const float* mbase = mask + (size_t)(base + i0 + w) * C + 2 * lane;
    // mk/sk2 hold tile "next to fill"
    float2 sk2 = *(const float2*)&g_sk[base + 2 * lane];
    float2 mk[8];
    #pragma unroll
    for (int s = 0; s < 8; s++)
        mk[s] = *(const float2*)(mbase + (size_t)(8 * s) * C);

    // fill tile 0 into buf 0 (probs consume mk=tile0, then prefetch tile1)
    {
        #pragma unroll
        for (int s = 0; s < 8; s++) {
            int row = w + 8 * s;
            float q = ssq[row];
            float x0 = q + sk2.x; x0 = (x0 >= 0.f) ? x0 : 0.01f * x0; x0 *= mk[s].x;
            float x1 = q + sk2.y; x1 = (x1 >= 0.f) ? x1 : 0.01f * x1; x1 *= mk[s].y;
            float p0 = __expf(x0), p1 = __expf(x1);
            rowsum[s] += p0 + p1;
            uint32_t pr; CVT_BF16X2(pr, p0 - 1.f, p1 - 1.f);
            *(uint32_t*)(pA[0] + SWZ(row * 128 + lane * 4)) = pr;
        }
        sk2 = *(const float2*)&g_sk[base + 64 + 2 * lane];
        #pragma unroll
        for (int s = 0; s < 8; s++)
            mk[s] = *(const float2*)(mbase + 64 + (size_t)(8 * s) * C);
        #pragma unroll
        for (int c = 0; c < 4; c++) {
            int idx = t + c * 256;
            int dd = idx >> 3, ccx = idx & 7;
            uint4 val = *(const uint4*)(vTb + (size_t)dd * C + ccx * 8);
            *(uint4*)(pB[0] + SWZ(dd * 128 + ccx * 16)) = val;
        }
    }
    __syncthreads();

    // ---- mainloop: fill next buffer, then MMA current; one sync per tile ----
    for (int i = 0; i < C / 64; i++) {
        int cur = i & 1, nxt = cur ^ 1;
        if (i + 1 < C / 64) {
            // probs for tile i+1 from prefetched regs
            #pragma unroll
            for (int s = 0; s < 8; s++) {
                int row = w + 8 * s;
                float q = ssq[row];
                float x0 = q + sk2.x; x0 = (x0 >= 0.f) ? x0 : 0.01f * x0; x0 *= mk[s].x;
                float x1 = q + sk2.y; x1 = (x1 >= 0.f) ? x1 : 0.01f * x1; x1 *= mk[s].y;
                float p0 = __expf(x0), p1 = __expf(x1);
                rowsum[s] += p0 + p1;
                uint32_t pr; CVT_BF16X2(pr, p0 - 1.f, p1 - 1.f);
                *(uint32_t*)(pA[nxt] + SWZ(row * 128 + lane * 4)) = pr;
            }
            // prefetch tile i+2 mask/sk
            if (i + 2 < C / 64) {
                int jn = (i + 2) * 64;
                sk2 = *(const float2*)&g_sk[base + jn + 2 * lane];
                #pragma unroll
                for (int s = 0; s < 8; s++)
                    mk[s] = *(const float2*)(mbase + jn + (size_t)(8 * s) * C);
            }
            // B tile i+1
            int jb = (i + 1) * 64;
            #pragma unroll
            for (int c = 0; c < 4; c++) {
                int idx = t + c * 256;
                int dd = idx >> 3, ccx = idx & 7;
                uint4 val = *(const uint4*)(vTb + (size_t)dd * C + jb + ccx * 8);
                *(uint4*)(pB[nxt] + SWZ(dd * 128 + ccx * 16)) = val;
            }
        }
        mma_pass64(sA[cur], sB[cur], cc, rowA, colAg, nh, rowBoff, colBg);
        __syncthreads();
    }

    // ---- rowsum reduce ----
    #pragma unroll
    for (int s = 0; s < 8; s++) {
        float r = rowsum[s];
        #pragma unroll
        for (int off = 16; off; off >>= 1) r += __shfl_down_sync(0xffffffffu, r, off);
        if (lane == 0) srow[w + 8 * s] = r;
    }
    __syncthreads();

    // ---- normalize weighted + stage bf16 into A0 (n<64) / A1 (n>=64) ----
    int quad = lane >> 2, qt = lane & 3;
    int m0 = (mg << 4) + quad;
    float inv0 = 1.0f / srow[m0];
    float inv8 = 1.0f / srow[m0 + 8];
    char* stg = pA[nh];
    #pragma unroll
    for (int nt = 0; nt < 8; nt++) {
        int n0 = (nh << 6) + nt * 8 + 2 * qt;
        float cs0 = scol[n0], cs1 = scol[n0 + 1];
        float w00 = (cs0 + cc[nt][0]) * inv0;
        float w01 = (cs1 + cc[nt][1]) * inv0;
        float w80 = (cs0 + cc[nt][2]) * inv8;
        float w81 = (cs1 + cc[nt][3]) * inv8;
        uint32_t pr0, pr8;
        CVT_BF16X2(pr0, w00, w01);
        CVT_BF16X2(pr8, w80, w81);
        uint32_t col = (nt * 8 + 2 * qt) * 2;
        *(uint32_t*)(stg + SWZ(m0 * 128 + col)) = pr0;
        *(uint32_t*)(stg + SWZ((m0 + 8) * 128 + col)) = pr8;
    }

    // ---- weighted @ Wc (hi-only), 2 K-chunks ----
    #pragma unroll
    for (int nt = 0; nt < 8; nt++)
        #pragma unroll
        for (int r = 0; r < 4; r++) cc[nt][r] = 0.f;

    #pragma unroll 1
    for (int c = 0; c < 2; c++) {
        __syncthreads();
        #pragma unroll
        for (int c2 = 0; c2 < 4; c2++) {
            int idx = t + c2 * 256;
            int dd = idx >> 3, ccx = idx & 7;
            *(uint4*)(pB[0] + SWZ(dd * 128 + ccx * 16)) =
                *(const uint4*)&g_Wch[dd * 128 + c * 64 + ccx * 8];
        }
        __syncthreads();
        mma_pass64(sA[c], sB[0], cc, rowA, colAg, nh, rowBoff, colBg);
    }

    // ---- epilogue ----
    int r0g = i0 + m0;
    size_t bb = (size_t)b * C * D;
    const float* m1 = g_mx + bb;
    const float* m2 = g_mx + BCD + bb;
    const float* m3 = g_mx + 2 * BCD + bb;
    float* ob = out + bb;

    #pragma unroll
    for (int half = 0; half < 2; half++) {
        int rg = r0g + half * 8;
        int loc = rg - i0;
        if (rg < CM2) {
            int2 rr = srel[loc];
            const float* pa = m1 + (size_t)rg * D;
            const float* pb = m2 + (size_t)rr.x * D;
            const float* pc = m3 + (size_t)rr.y * D;
            #pragma unroll
            for (int nt = 0; nt < 8; nt++) {
                int n0 = (nh << 6) + nt * 8 + 2 * qt;
                float2 a2 = *(const float2*)(pa + n0);
                float2 b2 = *(const float2*)(pb + n0);
                float2 c2v = *(const float2*)(pc + n0);
                float vx = a2.x + b2.x + c2v.x + sb3[n0] + cc[nt][2 * half];
                float vy = a2.y + b2.y + c2v.y + sb3[n0 + 1] + cc[nt][2 * half + 1];
                *(float2*)&ob[(size_t)rg * D + n0] = make_float2(vx, vy);
            }
        } else {
            const float* pe = g_beW + ((size_t)b * 2 + (rg - CM2)) * D;
            #pragma unroll
            for (int nt = 0; nt < 8; nt++) {
                int n0 = (nh << 6) + nt * 8 + 2 * qt;
                float2 ev = *(const float2*)(pe + n0);
                *(float2*)&ob[(size_t)rg * D + n0] =
                    make_float2(ev.x + cc[nt][2 * half],
                                ev.y + cc[nt][2 * half + 1]);
            }
        }
    }
}

// ---------------- launch ----------------
extern "C" void kernel_launch(void* const* d_in, const int* in_sizes, int n_in,
                              void* d_out, int out_size) {
    const float* ops      = (const float*)d_in[0];
    const int*   rel      = (const int*)d_in[1];
    const int*   bidx     = (const int*)d_in[2];
    const int*   eidx     = (const int*)d_in[3];
    const float* mask     = (const float*)d_in[4];
    const float* W_begin  = (const float*)d_in[5];
    const float* b_begin  = (const float*)d_in[6];
    const float* W_end    = (const float*)d_in[7];
    const float* b_end    = (const float*)d_in[8];
    const float* W_mix3   = (const float*)d_in[9];
    const float* b_mix3   = (const float*)d_in[10];
    const float* W_qkv    = (const float*)d_in[11];
    const float* b_qkv    = (const float*)d_in[12];
    const float* w_score  = (const float*)d_in[13];
    const float* b_score  = (const float*)d_in[14];
    const float* W_out    = (const float*)d_in[15];
    const float* b_out    = (const float*)d_in[16];
    const float* W_mix2   = (const float*)d_in[17];
    const float* b_mix2   = (const float*)d_in[18];
    float* out = (float*)d_out;

    static bool attr_set = false;
    if (!attr_set) {
        cudaFuncSetAttribute(k_gemm, cudaFuncAttributeMaxDynamicSharedMemorySize, SMEM_MMA2);
        cudaFuncSetAttribute(k_attn, cudaFuncAttributeMaxDynamicSharedMemorySize, SMEM_ATTN);
        attr_set = true;
    }

    k_pre<<<161, 128>>>(W_qkv, b_qkv, w_score, b_score, W_out, b_out,
                        W_mix2, b_mix2, W_mix3, b_mix3);
    k_gemm<<<1024 + 2 * B, 256, SMEM_MMA2>>>(ops, b_qkv, bidx, eidx,
                                             W_begin, b_begin, W_end, b_end, W_mix2);
    k_attn<<<256, 256, SMEM_ATTN>>>(mask, rel, out);
}